// round 15
// baseline (speedup 1.0000x reference)
#include <cuda_runtime.h>
#include <cuda_fp16.h>
#include <cstdint>

#define D      256
#define N1C    50000
#define E1C    800000
#define NDRUG  4096
#define E2C    131072
#define DD     (D*D)

#define NB1 ((N1C + 1023) / 1024)          // 49
#define NB2 ((NDRUG + 1023) / 1024)        // 4
#define NBSEG ((NDRUG + 1 + 1023) / 1024)  // 5
#define NTOT (NB1 + NB2 + NBSEG)           // 58 (single wave, grid-barrier safe)
#define TRBLK (8 * 8 * 14)                 // 896 transpose blocks
#define CNTBLK ((E1C + E2C) / 256)         // 3637 (exact)
#define GBLK ((N1C * 64) / 256)            // 12500 gather blocks (exact)

// ---------------- scratch (device globals; no allocation allowed) -------------
__device__ __half h_x[(size_t)N1C * D];
__device__ __half h_y[(size_t)N1C * D];
__device__ __half h_agg[(size_t)N1C * D];
__device__ __half h_gmax[NDRUG * D];
__device__ __half h_gmean[NDRUG * D];
__device__ __half h_xdrug[NDRUG * D];
__device__ __half h_x2a[NDRUG * D];
__device__ __half h_x2b[NDRUG * D];
__device__ __half h_agg2[NDRUG * D];
__device__ __half h_wt[14 * DD];          // transposed fp16 weights [N][K]

__device__ int g_cnt1i[N1C];              // self-zeroing (scan zeroes after read)
__device__ int g_base1[N1C + 1];
__device__ int g_cur1[N1C];
__device__ int g_csr1[E1C];
__device__ int g_part1[64];

__device__ int g_cnt2i[NDRUG];            // self-zeroing
__device__ int g_base2[NDRUG + 1];
__device__ int g_cur2[NDRUG];
__device__ int g_csr2[E2C];
__device__ int g_part2[64];

__device__ int g_bounds[NDRUG + 1];

// grid-barrier state (generation counter; self-resetting, replay-safe)
__device__ int g_bar_i;
__device__ int g_gen_i;

// PDL: wait for producer kernel completion before consuming its data.
__device__ __forceinline__ void pdl_wait() { cudaGridDependencySynchronize(); }
// PDL: allow the dependent kernel to start launching now (data still guarded
// by the consumer's pdl_wait, which waits for FULL completion of this kernel).
__device__ __forceinline__ void pdl_trigger() { cudaTriggerProgrammaticLaunchCompletion(); }

// ---------------- PTX helpers --------------------------------------------------
__device__ __forceinline__ void cp_async_z(uint32_t sa, const void* g, int sz) {
    asm volatile("cp.async.cg.shared.global [%0], [%1], 16, %2;"
                 :: "r"(sa), "l"(g), "r"(sz));
}
#define CP_COMMIT() asm volatile("cp.async.commit_group;" ::: "memory")
#define CP_WAIT0()  asm volatile("cp.async.wait_group 0;" ::: "memory")

__device__ __forceinline__ void ldm_x4(uint32_t* r, uint32_t addr) {
    asm volatile("ldmatrix.sync.aligned.m8n8.x4.shared.b16 {%0,%1,%2,%3}, [%4];"
                 : "=r"(r[0]), "=r"(r[1]), "=r"(r[2]), "=r"(r[3]) : "r"(addr));
}
__device__ __forceinline__ void ldm_x2(uint32_t* r, uint32_t addr) {
    asm volatile("ldmatrix.sync.aligned.m8n8.x2.shared.b16 {%0,%1}, [%2];"
                 : "=r"(r[0]), "=r"(r[1]) : "r"(addr));
}
__device__ __forceinline__ void mma_f16(float* c, const uint32_t* a, const uint32_t* b) {
    asm volatile(
        "mma.sync.aligned.m16n8k16.row.col.f32.f16.f16.f32 "
        "{%0,%1,%2,%3}, {%4,%5,%6,%7}, {%8,%9}, {%0,%1,%2,%3};"
        : "+f"(c[0]), "+f"(c[1]), "+f"(c[2]), "+f"(c[3])
        : "r"(a[0]), "r"(a[1]), "r"(a[2]), "r"(a[3]), "r"(b[0]), "r"(b[1]));
}

// single-edge fp32 accumulate (exact tail path)
#define ACCUM(V) do { \
    float2 f; \
    f = __half22float2(*(__half2*)&(V).x); a0.x += f.x; a0.y += f.y; \
    f = __half22float2(*(__half2*)&(V).y); a1.x += f.x; a1.y += f.y; \
    f = __half22float2(*(__half2*)&(V).z); a2.x += f.x; a2.y += f.y; \
    f = __half22float2(*(__half2*)&(V).w); a3.x += f.x; a3.y += f.y; \
} while (0)

// pair accumulate: fp16 pre-sum (1 rounding), then fp32 add
#define PACC(VA, VB) do { \
    __half2 s0 = __hadd2(*(__half2*)&(VA).x, *(__half2*)&(VB).x); \
    __half2 s1 = __hadd2(*(__half2*)&(VA).y, *(__half2*)&(VB).y); \
    __half2 s2 = __hadd2(*(__half2*)&(VA).z, *(__half2*)&(VB).z); \
    __half2 s3 = __hadd2(*(__half2*)&(VA).w, *(__half2*)&(VB).w); \
    float2 f; \
    f = __half22float2(s0); a0.x += f.x; a0.y += f.y; \
    f = __half22float2(s1); a1.x += f.x; a1.y += f.y; \
    f = __half22float2(s2); a2.x += f.x; a2.y += f.y; \
    f = __half22float2(s3); a3.x += f.x; a3.y += f.y; \
} while (0)

// ---------------- fp16 tensor-core GEMM ----------------------------------------
#define ROWB 80
#define TILE_B (128 * ROWB)
#define GEMM_SMEM (4 * TILE_B)

__global__ void __launch_bounds__(256, 2) gemm_h(
    const __half* A0, const __half* B0,
    const __half* A1, const __half* B1,
    const __half* A2, const __half* B2,
    const float* __restrict__ bias,
    float* __restrict__ Cf, __half* __restrict__ Ch, int M, int nseg) {
    extern __shared__ char sm[];
    const uint32_t smBase = (uint32_t)__cvta_generic_to_shared(sm);
    const uint32_t aBase[2] = { smBase, smBase + TILE_B };
    const uint32_t bBase[2] = { smBase + 2 * TILE_B, smBase + 3 * TILE_B };

    const int tid = threadIdx.x;
    const int wid = tid >> 5;
    const int lane = tid & 31;
    const int g = lane >> 2;
    const int tq = lane & 3;
    const int wm = (wid >> 2) * 64;
    const int wn = (wid & 3) * 32;
    const int m0 = blockIdx.y * 128;
    const int n0 = blockIdx.x * 128;

    uint32_t aoff[4], boff[4];
#pragma unroll
    for (int mt = 0; mt < 4; mt++)
        aoff[mt] = (uint32_t)((wm + mt * 16 + (lane & 15)) * ROWB + ((lane & 16) ? 16 : 0));
#pragma unroll
    for (int nt = 0; nt < 4; nt++)
        boff[nt] = (uint32_t)((wn + nt * 8 + (lane & 7)) * ROWB + ((lane & 8) ? 16 : 0));

    float acc[4][4][4];
#pragma unroll
    for (int mt = 0; mt < 4; mt++)
#pragma unroll
        for (int nt = 0; nt < 4; nt++)
#pragma unroll
            for (int q = 0; q < 4; q++) acc[mt][nt][q] = 0.f;

    const __half* Aseg[3] = { A0, A1, A2 };
    const __half* Bseg[3] = { B0, B1, B2 };
    const int total = nseg * 8;

    const int c0i = tid * 2;
    const int row0 = c0i >> 2, off0 = (c0i & 3) * 16;
    const int row1 = (c0i + 1) >> 2, off1 = ((c0i + 1) & 3) * 16;

    pdl_wait();   // producer (aggregate/pool) must be complete before reading A

#define STAGE(buf, tile) do { \
    const __half* A = Aseg[(tile) >> 3]; \
    const __half* B = Bseg[(tile) >> 3]; \
    const int kh = ((tile) & 7) * 32; \
    cp_async_z(aBase[buf] + row0 * ROWB + off0, \
               (const char*)(A + (size_t)(m0 + row0) * D + kh) + off0, \
               (m0 + row0 < M) ? 16 : 0); \
    cp_async_z(aBase[buf] + row1 * ROWB + off1, \
               (const char*)(A + (size_t)(m0 + row1) * D + kh) + off1, \
               (m0 + row1 < M) ? 16 : 0); \
    cp_async_z(bBase[buf] + row0 * ROWB + off0, \
               (const char*)(B + (size_t)(n0 + row0) * D + kh) + off0, 16); \
    cp_async_z(bBase[buf] + row1 * ROWB + off1, \
               (const char*)(B + (size_t)(n0 + row1) * D + kh) + off1, 16); \
    CP_COMMIT(); \
} while (0)

    STAGE(0, 0);
    CP_WAIT0();
    __syncthreads();

    for (int t = 0; t < total; t++) {
        const int buf = t & 1;
        if (t + 1 < total) STAGE(buf ^ 1, t + 1);

        const uint32_t Ab = aBase[buf], Bb = bBase[buf];
#pragma unroll
        for (int ks = 0; ks < 2; ks++) {
            uint32_t af[4][4], bf[4][2];
#pragma unroll
            for (int mt = 0; mt < 4; mt++) ldm_x4(af[mt], Ab + aoff[mt] + ks * 32);
#pragma unroll
            for (int nt = 0; nt < 4; nt++) ldm_x2(bf[nt], Bb + boff[nt] + ks * 32);
#pragma unroll
            for (int mt = 0; mt < 4; mt++)
#pragma unroll
                for (int nt = 0; nt < 4; nt++)
                    mma_f16(acc[mt][nt], af[mt], bf[nt]);
        }

        if (t + 1 < total) {
            CP_WAIT0();
            __syncthreads();
        }
    }

    pdl_trigger();   // mainloop done: let the next kernel start launching

#pragma unroll
    for (int mt = 0; mt < 4; mt++) {
        int mlo = m0 + wm + mt * 16 + g;
#pragma unroll
        for (int nt = 0; nt < 4; nt++) {
            int n = n0 + wn + nt * 8 + tq * 2;
            float b0 = bias[n], b1 = bias[n + 1];
            float o0 = fmaxf(acc[mt][nt][0] + b0, 0.f);
            float o1 = fmaxf(acc[mt][nt][1] + b1, 0.f);
            float o2 = fmaxf(acc[mt][nt][2] + b0, 0.f);
            float o3 = fmaxf(acc[mt][nt][3] + b1, 0.f);
            if (Ch) {
                if (mlo < M)
                    *(__half2*)(Ch + (size_t)mlo * D + n) =
                        __float22half2_rn(make_float2(o0, o1));
                if (mlo + 8 < M)
                    *(__half2*)(Ch + (size_t)(mlo + 8) * D + n) =
                        __float22half2_rn(make_float2(o2, o3));
            } else {
                if (mlo < M)
                    *(float2*)(Cf + (size_t)mlo * D + n) = make_float2(o0, o1);
                if (mlo + 8 < M)
                    *(float2*)(Cf + (size_t)(mlo + 8) * D + n) = make_float2(o2, o3);
            }
        }
    }
}

// ---------------- phase-0: transpose + count + emb1 gather (merged) ------------
struct WTP { const float* src[14]; __half* dst[14]; };

__global__ void __launch_bounds__(256) count_tr_gather(
    WTP p, const int* __restrict__ dst1, const int* __restrict__ dst2,
    int* __restrict__ cnt1, int* __restrict__ cnt2,
    const float* __restrict__ emb, const int* __restrict__ ids,
    __half* __restrict__ xout) {
    __shared__ float t[32][33];
    int b = blockIdx.x;
    if (b < TRBLK) {
        int z = b >> 6, rem = b & 63;
        int by = rem >> 3, bx = rem & 7;
        int tx = threadIdx.x & 31, ty = threadIdx.x >> 5;
        const float* src = p.src[z];
        __half* dst = p.dst[z];
        int xx = bx * 32 + tx;
        int y0 = by * 32 + ty;
#pragma unroll
        for (int i = 0; i < 32; i += 8)
            t[ty + i][tx] = src[(size_t)(y0 + i) * D + xx];
        __syncthreads();
        int x2 = by * 32 + tx;
        int y2 = bx * 32 + ty;
#pragma unroll
        for (int i = 0; i < 32; i += 8)
            dst[(size_t)(y2 + i) * D + x2] = __float2half_rn(t[tx][ty + i]);
    } else if (b < TRBLK + CNTBLK) {
        int e = (b - TRBLK) * 256 + threadIdx.x;
        if (e < E1C) atomicAdd(&cnt1[dst1[e]], 1);
        else atomicAdd(&cnt2[dst2[e - E1C]], 1);
    } else {
        int q = (b - TRBLK - CNTBLK) * 256 + threadIdx.x;
        int i = q >> 6, c = q & 63;
        float4 v = ((const float4*)(emb + (size_t)ids[i] * D))[c];
        __half2 h0 = __float22half2_rn(make_float2(v.x, v.y));
        __half2 h1 = __float22half2_rn(make_float2(v.z, v.w));
        uint2 u;
        u.x = *(uint32_t*)&h0;
        u.y = *(uint32_t*)&h1;
        ((uint2*)(xout + (size_t)i * D))[c] = u;
    }
}

// ---------------- scan + add + seg_bounds in ONE kernel (grid barrier) ---------
__global__ void __launch_bounds__(1024) scan_add_both(
    int* __restrict__ cnt1, int* __restrict__ base1, int* __restrict__ cur1,
    int* __restrict__ part1,
    int* __restrict__ cnt2, int* __restrict__ base2, int* __restrict__ cur2,
    int* __restrict__ part2,
    const int* __restrict__ batch, int* __restrict__ bounds) {
    __shared__ int ws[32];
    __shared__ int sp[64];
    const int bx = blockIdx.x;
    const bool is_scan = bx < NB1 + NB2;

    pdl_wait();   // counts must be final

    if (is_scan) {
        int* cnt; int* out; int* partial; int n, b;
        if (bx < NB1) { cnt = cnt1; out = base1; partial = part1; n = N1C; b = bx; }
        else { cnt = cnt2; out = base2; partial = part2; n = NDRUG; b = bx - NB1; }
        int i = b * 1024 + threadIdx.x;
        int lane = threadIdx.x & 31, w = threadIdx.x >> 5;
        int v = 0;
        if (i < n) { v = cnt[i]; cnt[i] = 0; }
        int x = v;
#pragma unroll
        for (int o = 1; o < 32; o <<= 1) {
            int y = __shfl_up_sync(0xffffffffu, x, o);
            if (lane >= o) x += y;
        }
        if (lane == 31) ws[w] = x;
        __syncthreads();
        if (w == 0) {
            int t = ws[lane];
#pragma unroll
            for (int o = 1; o < 32; o <<= 1) {
                int y = __shfl_up_sync(0xffffffffu, t, o);
                if (lane >= o) t += y;
            }
            ws[lane] = t;
        }
        __syncthreads();
        int excl = x - v + (w ? ws[w - 1] : 0);
        if (i < n) out[i] = excl;
        if (threadIdx.x == 1023) partial[b] = excl + v;
    } else {
        int b = bx - NB1 - NB2;
        if (b == 0 && threadIdx.x == 0) {
            base1[N1C] = E1C;
            base2[NDRUG] = E2C;
        }
        int q = b * 1024 + threadIdx.x;
        if (q <= NDRUG) {
            int lo = 0, hi = N1C;
            while (lo < hi) {
                int mid = (lo + hi) >> 1;
                if (batch[mid] < q) lo = mid + 1; else hi = mid;
            }
            bounds[q] = lo;
        }
    }

    __syncthreads();
    if (threadIdx.x == 0) {
        int g0 = *(volatile int*)&g_gen_i;
        __threadfence();
        int old = atomicAdd(&g_bar_i, 1);
        if (old == NTOT - 1) {
            atomicExch(&g_bar_i, 0);
            __threadfence();
            atomicAdd(&g_gen_i, 1);
        } else if (is_scan) {
            while (*(volatile int*)&g_gen_i == g0) { }
        }
        ws[0] = 0;
    }
    __syncthreads();
    if (!is_scan) return;

    const int* part; int b;
    int* base; int* cur; int n;
    if (bx < NB1) { part = part1; b = bx; base = base1; cur = cur1; n = N1C; }
    else { part = part2; b = bx - NB1; base = base2; cur = cur2; n = NDRUG; }
    if (threadIdx.x < 64) sp[threadIdx.x] = (threadIdx.x < b) ? part[threadIdx.x] : 0;
    __syncthreads();
    if (threadIdx.x < 32) {
        int v = sp[threadIdx.x] + sp[threadIdx.x + 32];
#pragma unroll
        for (int o = 16; o > 0; o >>= 1)
            v += __shfl_down_sync(0xffffffffu, v, o);
        if (threadIdx.x == 0) sp[0] = v;
    }
    __syncthreads();
    int pref = sp[0];
    int i = b * 1024 + threadIdx.x;
    if (i < n) {
        int v = base[i] + pref;
        base[i] = v;
        cur[i] = v;
    }
}

// fill both CSR arrays, 2 edges / thread
__global__ void fill_both(const int* __restrict__ src1, const int* __restrict__ dst1,
                          int* __restrict__ cur1, int* __restrict__ csr1,
                          const int* __restrict__ src2, const int* __restrict__ dst2,
                          int* __restrict__ cur2, int* __restrict__ csr2) {
    int e0 = (blockIdx.x * blockDim.x + threadIdx.x) * 2;
    pdl_wait();   // cur arrays must be final
#pragma unroll
    for (int q = 0; q < 2; q++) {
        int e = e0 + q;
        if (e < E1C) {
            int p = atomicAdd(&cur1[dst1[e]], 1);
            csr1[p] = src1[e];
        } else {
            int e2 = e - E1C;
            if (e2 < E2C) {
                int p = atomicAdd(&cur2[dst2[e2]], 1);
                csr2[p] = src2[e2];
            }
        }
    }
}

// ---------------- small kernels -------------------------------------------------
__global__ void gather2_h(const __half* __restrict__ xdrug, const float* __restrict__ emb2,
                          const int* __restrict__ ids, __half* __restrict__ out) {
    int t = blockIdx.x * blockDim.x + threadIdx.x;
    int i = t >> 5, c = t & 31;
    if (i >= NDRUG) return;
    int id = ids[i];
    pdl_wait();
    uint4 u;
    if (id < NDRUG) {
        u = ((const uint4*)(xdrug + (size_t)id * D))[c];
    } else {
        const float4* r = (const float4*)(emb2 + (size_t)id * D);
        float4 a = r[c * 2], b = r[c * 2 + 1];
        __half2 h0 = __float22half2_rn(make_float2(a.x, a.y));
        __half2 h1 = __float22half2_rn(make_float2(a.z, a.w));
        __half2 h2 = __float22half2_rn(make_float2(b.x, b.y));
        __half2 h3 = __float22half2_rn(make_float2(b.z, b.w));
        u.x = *(uint32_t*)&h0; u.y = *(uint32_t*)&h1;
        u.z = *(uint32_t*)&h2; u.w = *(uint32_t*)&h3;
    }
    pdl_trigger();
    ((uint4*)(out + (size_t)i * D))[c] = u;
}

// warp-per-node mean aggregation; 2-edge PACC loop, register-lean for 8 CTAs/SM.
__global__ void __launch_bounds__(256, 8) aggregate_h(
    const __half* __restrict__ x, const int* __restrict__ csr,
    const int* __restrict__ base, __half* __restrict__ agg, int n) {
    int node = blockIdx.x * 8 + (threadIdx.x >> 5);
    int lane = threadIdx.x & 31;
    if (node >= n) return;
    pdl_wait();   // csr/base (or previous layer x) must be final
    int lo = base[node], hi = base[node + 1];
    float2 a0 = make_float2(0.f, 0.f), a1 = a0, a2 = a0, a3 = a0;
    int j = lo;
    for (; j + 1 < hi; j += 2) {
        uint4 v0 = ((const uint4*)(x + (size_t)csr[j] * D))[lane];
        uint4 v1 = ((const uint4*)(x + (size_t)csr[j + 1] * D))[lane];
        PACC(v0, v1);
    }
    if (j < hi) {
        uint4 v0 = ((const uint4*)(x + (size_t)csr[j] * D))[lane];
        ACCUM(v0);
    }
    pdl_trigger();   // edge loop done: let the paired GEMM start launching
    float r = 1.f / fmaxf((float)(hi - lo), 1.f);
    __half2 h0 = __float22half2_rn(make_float2(a0.x * r, a0.y * r));
    __half2 h1 = __float22half2_rn(make_float2(a1.x * r, a1.y * r));
    __half2 h2 = __float22half2_rn(make_float2(a2.x * r, a2.y * r));
    __half2 h3 = __float22half2_rn(make_float2(a3.x * r, a3.y * r));
    uint4 u;
    u.x = *(uint32_t*)&h0; u.y = *(uint32_t*)&h1;
    u.z = *(uint32_t*)&h2; u.w = *(uint32_t*)&h3;
    ((uint4*)(agg + (size_t)node * D))[lane] = u;
}

// warp-per-drug max + mean pooling
__global__ void __launch_bounds__(256) pool2_h(
    const __half* __restrict__ x, const int* __restrict__ bounds,
    __half* __restrict__ gmax, __half* __restrict__ gmean) {
    int drug = blockIdx.x * 8 + (threadIdx.x >> 5);
    int lane = threadIdx.x & 31;
    if (drug >= NDRUG) return;
    pdl_wait();
    int lo = bounds[drug], hi = bounds[drug + 1];
    float m[8], s[8];
#pragma unroll
    for (int q = 0; q < 8; q++) { m[q] = 0.f; s[q] = 0.f; }
    for (int i = lo; i < hi; i++) {
        uint4 v = ((const uint4*)(x + (size_t)i * D))[lane];
        const __half2* h = (const __half2*)&v;
#pragma unroll
        for (int q = 0; q < 4; q++) {
            float2 f = __half22float2(h[q]);
            m[q * 2]     = fmaxf(m[q * 2], f.x);
            m[q * 2 + 1] = fmaxf(m[q * 2 + 1], f.y);
            s[q * 2]     += f.x;
            s[q * 2 + 1] += f.y;
        }
    }
    pdl_trigger();
    float r = 1.f / fmaxf((float)(hi - lo), 1.f);
    uint4 um, us;
    __half2 t0, t1;
    t0 = __float22half2_rn(make_float2(m[0], m[1]));
    t1 = __float22half2_rn(make_float2(m[2], m[3]));
    um.x = *(uint32_t*)&t0; um.y = *(uint32_t*)&t1;
    t0 = __float22half2_rn(make_float2(m[4], m[5]));
    t1 = __float22half2_rn(make_float2(m[6], m[7]));
    um.z = *(uint32_t*)&t0; um.w = *(uint32_t*)&t1;
    t0 = __float22half2_rn(make_float2(s[0] * r, s[1] * r));
    t1 = __float22half2_rn(make_float2(s[2] * r, s[3] * r));
    us.x = *(uint32_t*)&t0; us.y = *(uint32_t*)&t1;
    t0 = __float22half2_rn(make_float2(s[4] * r, s[5] * r));
    t1 = __float22half2_rn(make_float2(s[6] * r, s[7] * r));
    us.z = *(uint32_t*)&t0; us.w = *(uint32_t*)&t1;
    ((uint4*)(gmax + (size_t)drug * D))[lane] = um;
    ((uint4*)(gmean + (size_t)drug * D))[lane] = us;
}

// ---------------- PDL launch helper --------------------------------------------
template <typename F, typename... Args>
static inline void launch_pdl(F f, dim3 grid, dim3 block, size_t smem,
                              cudaStream_t s, Args... args) {
    cudaLaunchConfig_t cfg = {};
    cfg.gridDim = grid;
    cfg.blockDim = block;
    cfg.dynamicSmemBytes = smem;
    cfg.stream = s;
    cudaLaunchAttribute attr[1];
    attr[0].id = cudaLaunchAttributeProgrammaticStreamSerialization;
    attr[0].val.programmaticStreamSerializationAllowed = 1;
    cfg.attrs = attr;
    cfg.numAttrs = 1;
    cudaLaunchKernelEx(&cfg, f, args...);
}

// ---------------- launch --------------------------------------------------------
extern "C" void kernel_launch(void* const* d_in, const int* in_sizes, int n_in,
                              void* d_out, int out_size) {
    const int* x1    = (const int*)d_in[0];
    const int* ei1   = (const int*)d_in[1];
    const int* batch = (const int*)d_in[2];
    const int* x2ids = (const int*)d_in[3];
    const int* ei2   = (const int*)d_in[4];
    const float* emb1  = (const float*)d_in[5];
    const float* emb2  = (const float*)d_in[6];
    const float* Wl1   = (const float*)d_in[7];
    const float* bl1   = (const float*)d_in[8];
    const float* Wr1   = (const float*)d_in[9];
    const float* lin1W = (const float*)d_in[10];
    const float* lin1b = (const float*)d_in[11];
    const float* Wl2   = (const float*)d_in[12];
    const float* bl2   = (const float*)d_in[13];
    const float* Wr2   = (const float*)d_in[14];
    const float* Wx2   = (const float*)d_in[15];

    const int* src1 = ei1;
    const int* dst1 = ei1 + E1C;
    const int* src2 = ei2;
    const int* dst2 = ei2 + E2C;

    __half *x, *y, *agg, *gmax, *gmean, *xdrug, *x2a, *x2b, *agg2, *wt;
    int *cnt1i, *base1, *cur1, *csr1, *part1;
    int *cnt2i, *base2, *cur2, *csr2, *part2, *bounds;
    cudaGetSymbolAddress((void**)&x, h_x);
    cudaGetSymbolAddress((void**)&y, h_y);
    cudaGetSymbolAddress((void**)&agg, h_agg);
    cudaGetSymbolAddress((void**)&gmax, h_gmax);
    cudaGetSymbolAddress((void**)&gmean, h_gmean);
    cudaGetSymbolAddress((void**)&xdrug, h_xdrug);
    cudaGetSymbolAddress((void**)&x2a, h_x2a);
    cudaGetSymbolAddress((void**)&x2b, h_x2b);
    cudaGetSymbolAddress((void**)&agg2, h_agg2);
    cudaGetSymbolAddress((void**)&wt, h_wt);
    cudaGetSymbolAddress((void**)&cnt1i, g_cnt1i);
    cudaGetSymbolAddress((void**)&base1, g_base1);
    cudaGetSymbolAddress((void**)&cur1, g_cur1);
    cudaGetSymbolAddress((void**)&csr1, g_csr1);
    cudaGetSymbolAddress((void**)&part1, g_part1);
    cudaGetSymbolAddress((void**)&cnt2i, g_cnt2i);
    cudaGetSymbolAddress((void**)&base2, g_base2);
    cudaGetSymbolAddress((void**)&cur2, g_cur2);
    cudaGetSymbolAddress((void**)&csr2, g_csr2);
    cudaGetSymbolAddress((void**)&part2, g_part2);
    cudaGetSymbolAddress((void**)&bounds, g_bounds);

    cudaFuncSetAttribute(gemm_h, cudaFuncAttributeMaxDynamicSharedMemorySize, GEMM_SMEM);

    cudaStream_t s = 0;

    // ---- phase 0: transpose weights + count degrees + gather emb1 (one kernel) ----
    WTP wp;
    for (int i = 0; i < 3; i++) { wp.src[i]     = Wl1 + (size_t)i * DD; }
    for (int i = 0; i < 3; i++) { wp.src[3 + i] = Wr1 + (size_t)i * DD; }
    wp.src[6] = lin1W;
    wp.src[7] = lin1W + (size_t)DD;
    for (int i = 0; i < 2; i++) { wp.src[8 + i]  = Wl2 + (size_t)i * DD; }
    for (int i = 0; i < 2; i++) { wp.src[10 + i] = Wr2 + (size_t)i * DD; }
    for (int i = 0; i < 2; i++) { wp.src[12 + i] = Wx2 + (size_t)i * DD; }
    for (int i = 0; i < 14; i++) wp.dst[i] = wt + (size_t)i * DD;
    count_tr_gather<<<TRBLK + CNTBLK + GBLK, 256, 0, s>>>(
        wp, dst1, dst2, cnt1i, cnt2i, emb1, x1, x);

    // ---- CSR build (PDL-chained) ----
    launch_pdl(scan_add_both, dim3(NTOT), dim3(1024), 0, s,
               cnt1i, base1, cur1, part1, cnt2i, base2, cur2, part2, batch, bounds);
    launch_pdl(fill_both, dim3((E1C + E2C + 511) / 512), dim3(256), 0, s,
               src1, dst1, cur1, csr1, src2, dst2, cur2, csr2);

    // ---- level 1: 3 SAGE layers (split aggregate + gemm, PDL-chained) ----
    __half* xin = x;
    __half* xout = y;
    const dim3 gg1(2, (N1C + 127) / 128);
    for (int i = 0; i < 3; i++) {
        launch_pdl(aggregate_h, dim3((N1C + 7) / 8), dim3(256), 0, s,
                   (const __half*)xin, (const int*)csr1, (const int*)base1, agg, N1C);
        launch_pdl(gemm_h, gg1, dim3(256), (size_t)GEMM_SMEM, s,
                   (const __half*)agg, (const __half*)(wt + (size_t)i * DD),
                   (const __half*)xin, (const __half*)(wt + (size_t)(3 + i) * DD),
                   (const __half*)nullptr, (const __half*)nullptr,
                   (const float*)(bl1 + (size_t)i * D),
                   (float*)nullptr, xout, N1C, 2);
        __half* t = xin; xin = xout; xout = t;
    }

    // ---- pooling + lin1 ----
    launch_pdl(pool2_h, dim3(NDRUG / 8), dim3(256), 0, s,
               (const __half*)xin, (const int*)bounds, gmax, gmean);
    launch_pdl(gemm_h, dim3(2, NDRUG / 128), dim3(256), (size_t)GEMM_SMEM, s,
               (const __half*)gmax, (const __half*)(wt + (size_t)6 * DD),
               (const __half*)gmean, (const __half*)(wt + (size_t)7 * DD),
               (const __half*)nullptr, (const __half*)nullptr,
               (const float*)lin1b, (float*)nullptr, xdrug, (int)NDRUG, 2);

    // ---- level 2 ----
    launch_pdl(gather2_h, dim3(((size_t)NDRUG * 32 + 255) / 256), dim3(256), 0, s,
               (const __half*)xdrug, emb2, x2ids, x2a);
    __half* x2in = x2a;
    for (int i = 0; i < 2; i++) {
        launch_pdl(aggregate_h, dim3((NDRUG + 7) / 8), dim3(256), 0, s,
                   (const __half*)x2in, (const int*)csr2, (const int*)base2, agg2, (int)NDRUG);
        if (i == 1) {
            launch_pdl(gemm_h, dim3(2, NDRUG / 128), dim3(256), (size_t)GEMM_SMEM, s,
                       (const __half*)agg2, (const __half*)(wt + (size_t)(8 + i) * DD),
                       (const __half*)x2in, (const __half*)(wt + (size_t)(10 + i) * DD),
                       (const __half*)xdrug, (const __half*)(wt + (size_t)(12 + i) * DD),
                       (const float*)(bl2 + (size_t)i * D),
                       (float*)d_out, (__half*)nullptr, (int)NDRUG, 3);
        } else {
            launch_pdl(gemm_h, dim3(2, NDRUG / 128), dim3(256), (size_t)GEMM_SMEM, s,
                       (const __half*)agg2, (const __half*)(wt + (size_t)(8 + i) * DD),
                       (const __half*)x2in, (const __half*)(wt + (size_t)(10 + i) * DD),
                       (const __half*)xdrug, (const __half*)(wt + (size_t)(12 + i) * DD),
                       (const float*)(bl2 + (size_t)i * D),
                       (float*)nullptr, x2b, (int)NDRUG, 3);
        }
        x2in = x2b;
    }
}

// round 16
// speedup vs baseline: 1.0831x; 1.0831x over previous
#include <cuda_runtime.h>
#include <cuda_fp16.h>
#include <cstdint>

#define D      256
#define N1C    50000
#define E1C    800000
#define NDRUG  4096
#define E2C    131072
#define DD     (D*D)

#define NB1 ((N1C + 1023) / 1024)          // 49
#define NB2 ((NDRUG + 1023) / 1024)        // 4
#define NBSEG ((NDRUG + 1 + 1023) / 1024)  // 5
#define NTOT (NB1 + NB2 + NBSEG)           // 58 (single wave, grid-barrier safe)
#define TRBLK (8 * 8 * 14)                 // 896 transpose blocks
#define CNTBLK ((E1C + E2C) / 256)         // 3637 (exact)
#define GBLK ((N1C * 64) / 256)            // 12500 gather blocks (exact)

// ---------------- scratch (device globals; no allocation allowed) -------------
__device__ __half h_x[(size_t)N1C * D];
__device__ __half h_y[(size_t)N1C * D];
__device__ __half h_agg[(size_t)N1C * D];
__device__ __half h_gmax[NDRUG * D];
__device__ __half h_gmean[NDRUG * D];
__device__ __half h_xdrug[NDRUG * D];
__device__ __half h_x2a[NDRUG * D];
__device__ __half h_x2b[NDRUG * D];
__device__ __half h_agg2[NDRUG * D];
__device__ __half h_wt[14 * DD];          // transposed fp16 weights [N][K]

__device__ int g_cnt1i[N1C];              // self-zeroing (scan zeroes after read)
__device__ int g_base1[N1C + 1];
__device__ int g_cur1[N1C];
__device__ int g_csr1[E1C];
__device__ int g_part1[64];

__device__ int g_cnt2i[NDRUG];            // self-zeroing
__device__ int g_base2[NDRUG + 1];
__device__ int g_cur2[NDRUG];
__device__ int g_csr2[E2C];
__device__ int g_part2[64];

__device__ int g_bounds[NDRUG + 1];

// grid-barrier state (generation counter; self-resetting, replay-safe)
__device__ int g_bar_i;
__device__ int g_gen_i;

// PDL: wait for producer kernel completion before consuming its data.
// No-op when the kernel was launched without the PDL attribute.
__device__ __forceinline__ void pdl_wait() { cudaGridDependencySynchronize(); }

// ---------------- PTX helpers --------------------------------------------------
__device__ __forceinline__ void cp_async_z(uint32_t sa, const void* g, int sz) {
    asm volatile("cp.async.cg.shared.global [%0], [%1], 16, %2;"
                 :: "r"(sa), "l"(g), "r"(sz));
}
#define CP_COMMIT() asm volatile("cp.async.commit_group;" ::: "memory")
#define CP_WAIT0()  asm volatile("cp.async.wait_group 0;" ::: "memory")

__device__ __forceinline__ void ldm_x4(uint32_t* r, uint32_t addr) {
    asm volatile("ldmatrix.sync.aligned.m8n8.x4.shared.b16 {%0,%1,%2,%3}, [%4];"
                 : "=r"(r[0]), "=r"(r[1]), "=r"(r[2]), "=r"(r[3]) : "r"(addr));
}
__device__ __forceinline__ void ldm_x2(uint32_t* r, uint32_t addr) {
    asm volatile("ldmatrix.sync.aligned.m8n8.x2.shared.b16 {%0,%1}, [%2];"
                 : "=r"(r[0]), "=r"(r[1]) : "r"(addr));
}
__device__ __forceinline__ void mma_f16(float* c, const uint32_t* a, const uint32_t* b) {
    asm volatile(
        "mma.sync.aligned.m16n8k16.row.col.f32.f16.f16.f32 "
        "{%0,%1,%2,%3}, {%4,%5,%6,%7}, {%8,%9}, {%0,%1,%2,%3};"
        : "+f"(c[0]), "+f"(c[1]), "+f"(c[2]), "+f"(c[3])
        : "r"(a[0]), "r"(a[1]), "r"(a[2]), "r"(a[3]), "r"(b[0]), "r"(b[1]));
}

// single-edge fp32 accumulate (exact tail path)
#define ACCUM(V) do { \
    float2 f; \
    f = __half22float2(*(__half2*)&(V).x); a0.x += f.x; a0.y += f.y; \
    f = __half22float2(*(__half2*)&(V).y); a1.x += f.x; a1.y += f.y; \
    f = __half22float2(*(__half2*)&(V).z); a2.x += f.x; a2.y += f.y; \
    f = __half22float2(*(__half2*)&(V).w); a3.x += f.x; a3.y += f.y; \
} while (0)

// pair accumulate: fp16 pre-sum (1 rounding), then fp32 add
#define PACC(VA, VB) do { \
    __half2 s0 = __hadd2(*(__half2*)&(VA).x, *(__half2*)&(VB).x); \
    __half2 s1 = __hadd2(*(__half2*)&(VA).y, *(__half2*)&(VB).y); \
    __half2 s2 = __hadd2(*(__half2*)&(VA).z, *(__half2*)&(VB).z); \
    __half2 s3 = __hadd2(*(__half2*)&(VA).w, *(__half2*)&(VB).w); \
    float2 f; \
    f = __half22float2(s0); a0.x += f.x; a0.y += f.y; \
    f = __half22float2(s1); a1.x += f.x; a1.y += f.y; \
    f = __half22float2(s2); a2.x += f.x; a2.y += f.y; \
    f = __half22float2(s3); a3.x += f.x; a3.y += f.y; \
} while (0)

// ---------------- fp16 tensor-core GEMM ----------------------------------------
#define ROWB 80
#define TILE_B (128 * ROWB)
#define GEMM_SMEM (4 * TILE_B)

__global__ void __launch_bounds__(256, 2) gemm_h(
    const __half* A0, const __half* B0,
    const __half* A1, const __half* B1,
    const __half* A2, const __half* B2,
    const float* __restrict__ bias,
    float* __restrict__ Cf, __half* __restrict__ Ch, int M, int nseg) {
    extern __shared__ char sm[];
    const uint32_t smBase = (uint32_t)__cvta_generic_to_shared(sm);
    const uint32_t aBase[2] = { smBase, smBase + TILE_B };
    const uint32_t bBase[2] = { smBase + 2 * TILE_B, smBase + 3 * TILE_B };

    const int tid = threadIdx.x;
    const int wid = tid >> 5;
    const int lane = tid & 31;
    const int g = lane >> 2;
    const int tq = lane & 3;
    const int wm = (wid >> 2) * 64;
    const int wn = (wid & 3) * 32;
    const int m0 = blockIdx.y * 128;
    const int n0 = blockIdx.x * 128;

    uint32_t aoff[4], boff[4];
#pragma unroll
    for (int mt = 0; mt < 4; mt++)
        aoff[mt] = (uint32_t)((wm + mt * 16 + (lane & 15)) * ROWB + ((lane & 16) ? 16 : 0));
#pragma unroll
    for (int nt = 0; nt < 4; nt++)
        boff[nt] = (uint32_t)((wn + nt * 8 + (lane & 7)) * ROWB + ((lane & 8) ? 16 : 0));

    float acc[4][4][4];
#pragma unroll
    for (int mt = 0; mt < 4; mt++)
#pragma unroll
        for (int nt = 0; nt < 4; nt++)
#pragma unroll
            for (int q = 0; q < 4; q++) acc[mt][nt][q] = 0.f;

    const __half* Aseg[3] = { A0, A1, A2 };
    const __half* Bseg[3] = { B0, B1, B2 };
    const int total = nseg * 8;

    const int c0i = tid * 2;
    const int row0 = c0i >> 2, off0 = (c0i & 3) * 16;
    const int row1 = (c0i + 1) >> 2, off1 = ((c0i + 1) & 3) * 16;

    pdl_wait();   // producer (aggregate/pool) must be complete before reading A

#define STAGE(buf, tile) do { \
    const __half* A = Aseg[(tile) >> 3]; \
    const __half* B = Bseg[(tile) >> 3]; \
    const int kh = ((tile) & 7) * 32; \
    cp_async_z(aBase[buf] + row0 * ROWB + off0, \
               (const char*)(A + (size_t)(m0 + row0) * D + kh) + off0, \
               (m0 + row0 < M) ? 16 : 0); \
    cp_async_z(aBase[buf] + row1 * ROWB + off1, \
               (const char*)(A + (size_t)(m0 + row1) * D + kh) + off1, \
               (m0 + row1 < M) ? 16 : 0); \
    cp_async_z(bBase[buf] + row0 * ROWB + off0, \
               (const char*)(B + (size_t)(n0 + row0) * D + kh) + off0, 16); \
    cp_async_z(bBase[buf] + row1 * ROWB + off1, \
               (const char*)(B + (size_t)(n0 + row1) * D + kh) + off1, 16); \
    CP_COMMIT(); \
} while (0)

    STAGE(0, 0);
    CP_WAIT0();
    __syncthreads();

    for (int t = 0; t < total; t++) {
        const int buf = t & 1;
        if (t + 1 < total) STAGE(buf ^ 1, t + 1);

        const uint32_t Ab = aBase[buf], Bb = bBase[buf];
#pragma unroll
        for (int ks = 0; ks < 2; ks++) {
            uint32_t af[4][4], bf[4][2];
#pragma unroll
            for (int mt = 0; mt < 4; mt++) ldm_x4(af[mt], Ab + aoff[mt] + ks * 32);
#pragma unroll
            for (int nt = 0; nt < 4; nt++) ldm_x2(bf[nt], Bb + boff[nt] + ks * 32);
#pragma unroll
            for (int mt = 0; mt < 4; mt++)
#pragma unroll
                for (int nt = 0; nt < 4; nt++)
                    mma_f16(acc[mt][nt], af[mt], bf[nt]);
        }

        if (t + 1 < total) {
            CP_WAIT0();
            __syncthreads();
        }
    }

#pragma unroll
    for (int mt = 0; mt < 4; mt++) {
        int mlo = m0 + wm + mt * 16 + g;
#pragma unroll
        for (int nt = 0; nt < 4; nt++) {
            int n = n0 + wn + nt * 8 + tq * 2;
            float b0 = bias[n], b1 = bias[n + 1];
            float o0 = fmaxf(acc[mt][nt][0] + b0, 0.f);
            float o1 = fmaxf(acc[mt][nt][1] + b1, 0.f);
            float o2 = fmaxf(acc[mt][nt][2] + b0, 0.f);
            float o3 = fmaxf(acc[mt][nt][3] + b1, 0.f);
            if (Ch) {
                if (mlo < M)
                    *(__half2*)(Ch + (size_t)mlo * D + n) =
                        __float22half2_rn(make_float2(o0, o1));
                if (mlo + 8 < M)
                    *(__half2*)(Ch + (size_t)(mlo + 8) * D + n) =
                        __float22half2_rn(make_float2(o2, o3));
            } else {
                if (mlo < M)
                    *(float2*)(Cf + (size_t)mlo * D + n) = make_float2(o0, o1);
                if (mlo + 8 < M)
                    *(float2*)(Cf + (size_t)(mlo + 8) * D + n) = make_float2(o2, o3);
            }
        }
    }
}

// ---------------- phase-0: transpose + count + emb1 gather (merged) ------------
struct WTP { const float* src[14]; __half* dst[14]; };

__global__ void __launch_bounds__(256) count_tr_gather(
    WTP p, const int* __restrict__ dst1, const int* __restrict__ dst2,
    int* __restrict__ cnt1, int* __restrict__ cnt2,
    const float* __restrict__ emb, const int* __restrict__ ids,
    __half* __restrict__ xout) {
    __shared__ float t[32][33];
    int b = blockIdx.x;
    if (b < TRBLK) {
        int z = b >> 6, rem = b & 63;
        int by = rem >> 3, bx = rem & 7;
        int tx = threadIdx.x & 31, ty = threadIdx.x >> 5;
        const float* src = p.src[z];
        __half* dst = p.dst[z];
        int xx = bx * 32 + tx;
        int y0 = by * 32 + ty;
#pragma unroll
        for (int i = 0; i < 32; i += 8)
            t[ty + i][tx] = src[(size_t)(y0 + i) * D + xx];
        __syncthreads();
        int x2 = by * 32 + tx;
        int y2 = bx * 32 + ty;
#pragma unroll
        for (int i = 0; i < 32; i += 8)
            dst[(size_t)(y2 + i) * D + x2] = __float2half_rn(t[tx][ty + i]);
    } else if (b < TRBLK + CNTBLK) {
        int e = (b - TRBLK) * 256 + threadIdx.x;
        if (e < E1C) atomicAdd(&cnt1[dst1[e]], 1);
        else atomicAdd(&cnt2[dst2[e - E1C]], 1);
    } else {
        int q = (b - TRBLK - CNTBLK) * 256 + threadIdx.x;
        int i = q >> 6, c = q & 63;
        float4 v = ((const float4*)(emb + (size_t)ids[i] * D))[c];
        __half2 h0 = __float22half2_rn(make_float2(v.x, v.y));
        __half2 h1 = __float22half2_rn(make_float2(v.z, v.w));
        uint2 u;
        u.x = *(uint32_t*)&h0;
        u.y = *(uint32_t*)&h1;
        ((uint2*)(xout + (size_t)i * D))[c] = u;
    }
}

// ---------------- scan + add + seg_bounds in ONE kernel (grid barrier) ---------
__global__ void __launch_bounds__(1024) scan_add_both(
    int* __restrict__ cnt1, int* __restrict__ base1, int* __restrict__ cur1,
    int* __restrict__ part1,
    int* __restrict__ cnt2, int* __restrict__ base2, int* __restrict__ cur2,
    int* __restrict__ part2,
    const int* __restrict__ batch, int* __restrict__ bounds) {
    __shared__ int ws[32];
    __shared__ int sp[64];
    const int bx = blockIdx.x;
    const bool is_scan = bx < NB1 + NB2;

    pdl_wait();   // counts must be final

    if (is_scan) {
        int* cnt; int* out; int* partial; int n, b;
        if (bx < NB1) { cnt = cnt1; out = base1; partial = part1; n = N1C; b = bx; }
        else { cnt = cnt2; out = base2; partial = part2; n = NDRUG; b = bx - NB1; }
        int i = b * 1024 + threadIdx.x;
        int lane = threadIdx.x & 31, w = threadIdx.x >> 5;
        int v = 0;
        if (i < n) { v = cnt[i]; cnt[i] = 0; }
        int x = v;
#pragma unroll
        for (int o = 1; o < 32; o <<= 1) {
            int y = __shfl_up_sync(0xffffffffu, x, o);
            if (lane >= o) x += y;
        }
        if (lane == 31) ws[w] = x;
        __syncthreads();
        if (w == 0) {
            int t = ws[lane];
#pragma unroll
            for (int o = 1; o < 32; o <<= 1) {
                int y = __shfl_up_sync(0xffffffffu, t, o);
                if (lane >= o) t += y;
            }
            ws[lane] = t;
        }
        __syncthreads();
        int excl = x - v + (w ? ws[w - 1] : 0);
        if (i < n) out[i] = excl;
        if (threadIdx.x == 1023) partial[b] = excl + v;
    } else {
        int b = bx - NB1 - NB2;
        if (b == 0 && threadIdx.x == 0) {
            base1[N1C] = E1C;
            base2[NDRUG] = E2C;
        }
        int q = b * 1024 + threadIdx.x;
        if (q <= NDRUG) {
            int lo = 0, hi = N1C;
            while (lo < hi) {
                int mid = (lo + hi) >> 1;
                if (batch[mid] < q) lo = mid + 1; else hi = mid;
            }
            bounds[q] = lo;
        }
    }

    __syncthreads();
    if (threadIdx.x == 0) {
        int g0 = *(volatile int*)&g_gen_i;
        __threadfence();
        int old = atomicAdd(&g_bar_i, 1);
        if (old == NTOT - 1) {
            atomicExch(&g_bar_i, 0);
            __threadfence();
            atomicAdd(&g_gen_i, 1);
        } else if (is_scan) {
            while (*(volatile int*)&g_gen_i == g0) { }
        }
        ws[0] = 0;
    }
    __syncthreads();
    if (!is_scan) return;

    const int* part; int b;
    int* base; int* cur; int n;
    if (bx < NB1) { part = part1; b = bx; base = base1; cur = cur1; n = N1C; }
    else { part = part2; b = bx - NB1; base = base2; cur = cur2; n = NDRUG; }
    if (threadIdx.x < 64) sp[threadIdx.x] = (threadIdx.x < b) ? part[threadIdx.x] : 0;
    __syncthreads();
    if (threadIdx.x < 32) {
        int v = sp[threadIdx.x] + sp[threadIdx.x + 32];
#pragma unroll
        for (int o = 16; o > 0; o >>= 1)
            v += __shfl_down_sync(0xffffffffu, v, o);
        if (threadIdx.x == 0) sp[0] = v;
    }
    __syncthreads();
    int pref = sp[0];
    int i = b * 1024 + threadIdx.x;
    if (i < n) {
        int v = base[i] + pref;
        base[i] = v;
        cur[i] = v;
    }
}

// fill both CSR arrays, 2 edges / thread
__global__ void fill_both(const int* __restrict__ src1, const int* __restrict__ dst1,
                          int* __restrict__ cur1, int* __restrict__ csr1,
                          const int* __restrict__ src2, const int* __restrict__ dst2,
                          int* __restrict__ cur2, int* __restrict__ csr2) {
    int e0 = (blockIdx.x * blockDim.x + threadIdx.x) * 2;
    pdl_wait();   // cur arrays must be final
#pragma unroll
    for (int q = 0; q < 2; q++) {
        int e = e0 + q;
        if (e < E1C) {
            int p = atomicAdd(&cur1[dst1[e]], 1);
            csr1[p] = src1[e];
        } else {
            int e2 = e - E1C;
            if (e2 < E2C) {
                int p = atomicAdd(&cur2[dst2[e2]], 1);
                csr2[p] = src2[e2];
            }
        }
    }
}

// ---------------- small kernels -------------------------------------------------
__global__ void gather2_h(const __half* __restrict__ xdrug, const float* __restrict__ emb2,
                          const int* __restrict__ ids, __half* __restrict__ out) {
    int t = blockIdx.x * blockDim.x + threadIdx.x;
    int i = t >> 5, c = t & 31;
    if (i >= NDRUG) return;
    int id = ids[i];
    pdl_wait();
    uint4 u;
    if (id < NDRUG) {
        u = ((const uint4*)(xdrug + (size_t)id * D))[c];
    } else {
        const float4* r = (const float4*)(emb2 + (size_t)id * D);
        float4 a = r[c * 2], b = r[c * 2 + 1];
        __half2 h0 = __float22half2_rn(make_float2(a.x, a.y));
        __half2 h1 = __float22half2_rn(make_float2(a.z, a.w));
        __half2 h2 = __float22half2_rn(make_float2(b.x, b.y));
        __half2 h3 = __float22half2_rn(make_float2(b.z, b.w));
        u.x = *(uint32_t*)&h0; u.y = *(uint32_t*)&h1;
        u.z = *(uint32_t*)&h2; u.w = *(uint32_t*)&h3;
    }
    ((uint4*)(out + (size_t)i * D))[c] = u;
}

// warp-per-node mean aggregation; 2-edge PACC loop, register-lean for 8 CTAs/SM.
__global__ void __launch_bounds__(256, 8) aggregate_h(
    const __half* __restrict__ x, const int* __restrict__ csr,
    const int* __restrict__ base, __half* __restrict__ agg, int n) {
    int node = blockIdx.x * 8 + (threadIdx.x >> 5);
    int lane = threadIdx.x & 31;
    if (node >= n) return;
    pdl_wait();   // csr/base (or previous layer x) must be final
    int lo = base[node], hi = base[node + 1];
    float2 a0 = make_float2(0.f, 0.f), a1 = a0, a2 = a0, a3 = a0;
    int j = lo;
    for (; j + 1 < hi; j += 2) {
        uint4 v0 = ((const uint4*)(x + (size_t)csr[j] * D))[lane];
        uint4 v1 = ((const uint4*)(x + (size_t)csr[j + 1] * D))[lane];
        PACC(v0, v1);
    }
    if (j < hi) {
        uint4 v0 = ((const uint4*)(x + (size_t)csr[j] * D))[lane];
        ACCUM(v0);
    }
    float r = 1.f / fmaxf((float)(hi - lo), 1.f);
    __half2 h0 = __float22half2_rn(make_float2(a0.x * r, a0.y * r));
    __half2 h1 = __float22half2_rn(make_float2(a1.x * r, a1.y * r));
    __half2 h2 = __float22half2_rn(make_float2(a2.x * r, a2.y * r));
    __half2 h3 = __float22half2_rn(make_float2(a3.x * r, a3.y * r));
    uint4 u;
    u.x = *(uint32_t*)&h0; u.y = *(uint32_t*)&h1;
    u.z = *(uint32_t*)&h2; u.w = *(uint32_t*)&h3;
    ((uint4*)(agg + (size_t)node * D))[lane] = u;
}

// warp-per-drug max + mean pooling
__global__ void __launch_bounds__(256) pool2_h(
    const __half* __restrict__ x, const int* __restrict__ bounds,
    __half* __restrict__ gmax, __half* __restrict__ gmean) {
    int drug = blockIdx.x * 8 + (threadIdx.x >> 5);
    int lane = threadIdx.x & 31;
    if (drug >= NDRUG) return;
    pdl_wait();
    int lo = bounds[drug], hi = bounds[drug + 1];
    float m[8], s[8];
#pragma unroll
    for (int q = 0; q < 8; q++) { m[q] = 0.f; s[q] = 0.f; }
    for (int i = lo; i < hi; i++) {
        uint4 v = ((const uint4*)(x + (size_t)i * D))[lane];
        const __half2* h = (const __half2*)&v;
#pragma unroll
        for (int q = 0; q < 4; q++) {
            float2 f = __half22float2(h[q]);
            m[q * 2]     = fmaxf(m[q * 2], f.x);
            m[q * 2 + 1] = fmaxf(m[q * 2 + 1], f.y);
            s[q * 2]     += f.x;
            s[q * 2 + 1] += f.y;
        }
    }
    float r = 1.f / fmaxf((float)(hi - lo), 1.f);
    uint4 um, us;
    __half2 t0, t1;
    t0 = __float22half2_rn(make_float2(m[0], m[1]));
    t1 = __float22half2_rn(make_float2(m[2], m[3]));
    um.x = *(uint32_t*)&t0; um.y = *(uint32_t*)&t1;
    t0 = __float22half2_rn(make_float2(m[4], m[5]));
    t1 = __float22half2_rn(make_float2(m[6], m[7]));
    um.z = *(uint32_t*)&t0; um.w = *(uint32_t*)&t1;
    t0 = __float22half2_rn(make_float2(s[0] * r, s[1] * r));
    t1 = __float22half2_rn(make_float2(s[2] * r, s[3] * r));
    us.x = *(uint32_t*)&t0; us.y = *(uint32_t*)&t1;
    t0 = __float22half2_rn(make_float2(s[4] * r, s[5] * r));
    t1 = __float22half2_rn(make_float2(s[6] * r, s[7] * r));
    us.z = *(uint32_t*)&t0; us.w = *(uint32_t*)&t1;
    ((uint4*)(gmax + (size_t)drug * D))[lane] = um;
    ((uint4*)(gmean + (size_t)drug * D))[lane] = us;
}

// ---------------- PDL launch helper --------------------------------------------
template <typename F, typename... Args>
static inline void launch_pdl(F f, dim3 grid, dim3 block, size_t smem,
                              cudaStream_t s, Args... args) {
    cudaLaunchConfig_t cfg = {};
    cfg.gridDim = grid;
    cfg.blockDim = block;
    cfg.dynamicSmemBytes = smem;
    cfg.stream = s;
    cudaLaunchAttribute attr[1];
    attr[0].id = cudaLaunchAttributeProgrammaticStreamSerialization;
    attr[0].val.programmaticStreamSerializationAllowed = 1;
    cfg.attrs = attr;
    cfg.numAttrs = 1;
    cudaLaunchKernelEx(&cfg, f, args...);
}

// ---------------- launch --------------------------------------------------------
extern "C" void kernel_launch(void* const* d_in, const int* in_sizes, int n_in,
                              void* d_out, int out_size) {
    const int* x1    = (const int*)d_in[0];
    const int* ei1   = (const int*)d_in[1];
    const int* batch = (const int*)d_in[2];
    const int* x2ids = (const int*)d_in[3];
    const int* ei2   = (const int*)d_in[4];
    const float* emb1  = (const float*)d_in[5];
    const float* emb2  = (const float*)d_in[6];
    const float* Wl1   = (const float*)d_in[7];
    const float* bl1   = (const float*)d_in[8];
    const float* Wr1   = (const float*)d_in[9];
    const float* lin1W = (const float*)d_in[10];
    const float* lin1b = (const float*)d_in[11];
    const float* Wl2   = (const float*)d_in[12];
    const float* bl2   = (const float*)d_in[13];
    const float* Wr2   = (const float*)d_in[14];
    const float* Wx2   = (const float*)d_in[15];

    const int* src1 = ei1;
    const int* dst1 = ei1 + E1C;
    const int* src2 = ei2;
    const int* dst2 = ei2 + E2C;

    __half *x, *y, *agg, *gmax, *gmean, *xdrug, *x2a, *x2b, *agg2, *wt;
    int *cnt1i, *base1, *cur1, *csr1, *part1;
    int *cnt2i, *base2, *cur2, *csr2, *part2, *bounds;
    cudaGetSymbolAddress((void**)&x, h_x);
    cudaGetSymbolAddress((void**)&y, h_y);
    cudaGetSymbolAddress((void**)&agg, h_agg);
    cudaGetSymbolAddress((void**)&gmax, h_gmax);
    cudaGetSymbolAddress((void**)&gmean, h_gmean);
    cudaGetSymbolAddress((void**)&xdrug, h_xdrug);
    cudaGetSymbolAddress((void**)&x2a, h_x2a);
    cudaGetSymbolAddress((void**)&x2b, h_x2b);
    cudaGetSymbolAddress((void**)&agg2, h_agg2);
    cudaGetSymbolAddress((void**)&wt, h_wt);
    cudaGetSymbolAddress((void**)&cnt1i, g_cnt1i);
    cudaGetSymbolAddress((void**)&base1, g_base1);
    cudaGetSymbolAddress((void**)&cur1, g_cur1);
    cudaGetSymbolAddress((void**)&csr1, g_csr1);
    cudaGetSymbolAddress((void**)&part1, g_part1);
    cudaGetSymbolAddress((void**)&cnt2i, g_cnt2i);
    cudaGetSymbolAddress((void**)&base2, g_base2);
    cudaGetSymbolAddress((void**)&cur2, g_cur2);
    cudaGetSymbolAddress((void**)&csr2, g_csr2);
    cudaGetSymbolAddress((void**)&part2, g_part2);
    cudaGetSymbolAddress((void**)&bounds, g_bounds);

    cudaFuncSetAttribute(gemm_h, cudaFuncAttributeMaxDynamicSharedMemorySize, GEMM_SMEM);

    cudaStream_t s = 0;

    // ---- phase 0: transpose weights + count degrees + gather emb1 (one kernel) ----
    WTP wp;
    for (int i = 0; i < 3; i++) { wp.src[i]     = Wl1 + (size_t)i * DD; }
    for (int i = 0; i < 3; i++) { wp.src[3 + i] = Wr1 + (size_t)i * DD; }
    wp.src[6] = lin1W;
    wp.src[7] = lin1W + (size_t)DD;
    for (int i = 0; i < 2; i++) { wp.src[8 + i]  = Wl2 + (size_t)i * DD; }
    for (int i = 0; i < 2; i++) { wp.src[10 + i] = Wr2 + (size_t)i * DD; }
    for (int i = 0; i < 2; i++) { wp.src[12 + i] = Wx2 + (size_t)i * DD; }
    for (int i = 0; i < 14; i++) wp.dst[i] = wt + (size_t)i * DD;
    count_tr_gather<<<TRBLK + CNTBLK + GBLK, 256, 0, s>>>(
        wp, dst1, dst2, cnt1i, cnt2i, emb1, x1, x);

    // ---- CSR build (PDL-chained) ----
    launch_pdl(scan_add_both, dim3(NTOT), dim3(1024), 0, s,
               cnt1i, base1, cur1, part1, cnt2i, base2, cur2, part2, batch, bounds);
    launch_pdl(fill_both, dim3((E1C + E2C + 511) / 512), dim3(256), 0, s,
               src1, dst1, cur1, csr1, src2, dst2, cur2, csr2);

    // ---- level 1: 3 SAGE layers (split aggregate + gemm, PDL-chained) ----
    __half* xin = x;
    __half* xout = y;
    const dim3 gg1(2, (N1C + 127) / 128);
    for (int i = 0; i < 3; i++) {
        launch_pdl(aggregate_h, dim3((N1C + 7) / 8), dim3(256), 0, s,
                   (const __half*)xin, (const int*)csr1, (const int*)base1, agg, N1C);
        launch_pdl(gemm_h, gg1, dim3(256), (size_t)GEMM_SMEM, s,
                   (const __half*)agg, (const __half*)(wt + (size_t)i * DD),
                   (const __half*)xin, (const __half*)(wt + (size_t)(3 + i) * DD),
                   (const __half*)nullptr, (const __half*)nullptr,
                   (const float*)(bl1 + (size_t)i * D),
                   (float*)nullptr, xout, N1C, 2);
        __half* t = xin; xin = xout; xout = t;
    }

    // ---- pooling + lin1 ----
    launch_pdl(pool2_h, dim3(NDRUG / 8), dim3(256), 0, s,
               (const __half*)xin, (const int*)bounds, gmax, gmean);
    launch_pdl(gemm_h, dim3(2, NDRUG / 128), dim3(256), (size_t)GEMM_SMEM, s,
               (const __half*)gmax, (const __half*)(wt + (size_t)6 * DD),
               (const __half*)gmean, (const __half*)(wt + (size_t)7 * DD),
               (const __half*)nullptr, (const __half*)nullptr,
               (const float*)lin1b, (float*)nullptr, xdrug, (int)NDRUG, 2);

    // ---- level 2 ----
    launch_pdl(gather2_h, dim3(((size_t)NDRUG * 32 + 255) / 256), dim3(256), 0, s,
               (const __half*)xdrug, emb2, x2ids, x2a);
    __half* x2in = x2a;
    for (int i = 0; i < 2; i++) {
        launch_pdl(aggregate_h, dim3((NDRUG + 7) / 8), dim3(256), 0, s,
                   (const __half*)x2in, (const int*)csr2, (const int*)base2, agg2, (int)NDRUG);
        if (i == 1) {
            launch_pdl(gemm_h, dim3(2, NDRUG / 128), dim3(256), (size_t)GEMM_SMEM, s,
                       (const __half*)agg2, (const __half*)(wt + (size_t)(8 + i) * DD),
                       (const __half*)x2in, (const __half*)(wt + (size_t)(10 + i) * DD),
                       (const __half*)xdrug, (const __half*)(wt + (size_t)(12 + i) * DD),
                       (const float*)(bl2 + (size_t)i * D),
                       (float*)d_out, (__half*)nullptr, (int)NDRUG, 3);
        } else {
            launch_pdl(gemm_h, dim3(2, NDRUG / 128), dim3(256), (size_t)GEMM_SMEM, s,
                       (const __half*)agg2, (const __half*)(wt + (size_t)(8 + i) * DD),
                       (const __half*)x2in, (const __half*)(wt + (size_t)(10 + i) * DD),
                       (const __half*)xdrug, (const __half*)(wt + (size_t)(12 + i) * DD),
                       (const float*)(bl2 + (size_t)i * D),
                       (float*)nullptr, x2b, (int)NDRUG, 3);
        }
        x2in = x2b;
    }
}